// round 15
// baseline (speedup 1.0000x reference)
#include <cuda_runtime.h>
#include <math.h>

#define B 96
#define D 512

// ---------------- device scratch (no allocations allowed) ----------------
__device__ float              g_dist[B * B];
__device__ unsigned int       g_count  = 0u;    // grid-barrier ticket
__device__ unsigned int       g_count2 = 0u;    // final-sum ticket
__device__ unsigned long long g_acc    = 0ull;  // fixed-point (2^38) loss accumulator

#define FP_SCALE     274877906944.0f            /* 2^38 */
#define FP_INV_SCALE (1.0 / 274877906944.0)

// ---------------------------------------------------------------------------
// Single fused kernel. Block a (96 blocks, all co-resident):
//   phase 1: dist row a (32 warps x 3 cols, short FMA chains) -> g_dist + smem
//   phase 2: warp 1 mines row a while thread 0 runs the spin grid-barrier
//   phase 3: warp 1 computes the factorized inter term reading rows p,n of
//            g_dist (bitwise-symmetric => column p == row p), then folds the
//            final mean via deterministic int64 fixed-point atomics.
// ---------------------------------------------------------------------------
__global__ __launch_bounds__(1024, 1)
void k_all(const float* __restrict__ embs, const int* __restrict__ raw,
           float* __restrict__ out) {
    __shared__ float4 srow[D / 4];   // row a, 2 KB
    __shared__ float  drow[B];
    __shared__ int    sy[B];
    __shared__ int    s_bad;

    const int a    = blockIdx.x;
    const int tid  = threadIdx.x;
    const int w    = tid >> 5;
    const int lane = tid & 31;

    if (tid < D / 4) srow[tid] = ((const float4*)(embs + (size_t)a * D))[tid];
    if (tid == 0)    s_bad = 0;
    __syncthreads();

    // identity layout autodetect (int64-LE pairs look like (v<16, 0))
    if (tid < 48) {
        int lo = raw[2 * tid], hi = raw[2 * tid + 1];
        if (hi != 0 || (unsigned)lo >= 16u) s_bad = 1;   // benign race, same value
    }

    // ---- phase 1: distances, 3 columns per warp ----
#pragma unroll
    for (int c = 0; c < 3; c++) {
        const int j = w + 32 * c;
        const float4* rj = (const float4*)(embs + (size_t)j * D);
        float s0 = 0.f, s1 = 0.f, s2 = 0.f, s3 = 0.f;
#pragma unroll
        for (int q = 0; q < 4; q++) {
            float4 x = srow[lane + 32 * q];
            float4 b = rj[lane + 32 * q];
            float d0 = x.x - b.x, d1 = x.y - b.y, d2 = x.z - b.z, d3 = x.w - b.w;
            s0 += d0 * d0; s1 += d1 * d1; s2 += d2 * d2; s3 += d3 * d3;
        }
        float s = (s0 + s1) + (s2 + s3);
#pragma unroll
        for (int o = 16; o; o >>= 1) s += __shfl_xor_sync(0xffffffffu, s, o);
        if (lane == 0) {
            float dres = (a == j || s <= 0.0f) ? 0.0f : sqrtf(s);  // ref zero-handling
            drow[j] = dres;
            g_dist[a * B + j] = dres;
        }
    }
    if (lane == 0) __threadfence();  // release: only the 32 writers fence
    __syncthreads();                 // drow, s_bad, and all fences done
    if (tid < B) sy[tid] = s_bad ? raw[tid] : raw[2 * tid];
    __syncthreads();

    // ---- phase 2: warp 0/thread 0 runs the grid barrier; warp 1 mines ----
    if (tid == 0) {
        atomicAdd(&g_count, 1u);
        volatile unsigned* vc = &g_count;
        while (*vc < (unsigned)B) {}
        __threadfence();             // acquire: peer dist rows now visible
    }

    float trip = 0.0f;
    int p = 0, n = 0;
    if (w == 1) {
        const int yi = sy[a];
        float dv[3]; int yv[3];
#pragma unroll
        for (int q = 0; q < 3; q++) {
            int j = lane + 32 * q;
            dv[q] = drow[j];
            yv[q] = sy[j];
        }
        // unmasked row max (for the an_dist offset)
        float maxd = fmaxf(fmaxf(dv[0], dv[1]), dv[2]);
#pragma unroll
        for (int o = 16; o; o >>= 1)
            maxd = fmaxf(maxd, __shfl_xor_sync(0xffffffffu, maxd, o));

        // hardest positive: argmax over mask_ap*d, first-occurrence ties
        float pbest = -1.0f; int pidx = 1 << 20;
#pragma unroll
        for (int q = 0; q < 3; q++) {
            int j = lane + 32 * q;
            float apv = (j != a && yv[q] == yi) ? dv[q] : 0.0f;
            if (apv > pbest) { pbest = apv; pidx = j; }   // strict > keeps smallest j per lane
        }
#pragma unroll
        for (int o = 16; o; o >>= 1) {
            float ov = __shfl_xor_sync(0xffffffffu, pbest, o);
            int   oi = __shfl_xor_sync(0xffffffffu, pidx, o);
            if (ov > pbest || (ov == pbest && oi < pidx)) { pbest = ov; pidx = oi; }
        }

        // hardest negative: argmin over d + maxd*(1-mask_an), first-occurrence ties
        float nbest = 3.4e38f; int nidx = 1 << 20;
#pragma unroll
        for (int q = 0; q < 3; q++) {
            int j = lane + 32 * q;
            float anv = (yv[q] != yi) ? dv[q] : dv[q] + maxd;
            if (anv < nbest) { nbest = anv; nidx = j; }
        }
#pragma unroll
        for (int o = 16; o; o >>= 1) {
            float ov = __shfl_xor_sync(0xffffffffu, nbest, o);
            int   oi = __shfl_xor_sync(0xffffffffu, nidx, o);
            if (ov < nbest || (ov == nbest && oi < nidx)) { nbest = ov; nidx = oi; }
        }

        trip = fmaxf(pbest - nbest + 0.2f, 0.0f);   // all lanes hold result
        p = pidx; n = nidx;
    }
    __syncthreads();                 // barrier passed by all; dist matrix complete

    // ---- phase 3: inter term + final mean (warp 1 only) ----
    if (w == 1) {
        const int yp = sy[p], yn = sy[n];

        // M = max_{b != p, y_b == y_p} d[b][p]; dist is bitwise symmetric, so
        // read ROW p coalesced (L1-bypass: rows were written by other SMs).
        float M = -1.0f;             // stays -1 iff no valid b
#pragma unroll
        for (int q = 0; q < 3; q++) {
            int b = lane + 32 * q;
            float dpb = __ldcg(g_dist + p * B + b);
            if (b != p && sy[b] == yp) M = fmaxf(M, dpb);
        }
#pragma unroll
        for (int o = 16; o; o >>= 1)
            M = fmaxf(M, __shfl_xor_sync(0xffffffffu, M, o));

        float s = 0.0f;
        if (M >= 0.0f && yp != yn) {
#pragma unroll
            for (int q = 0; q < 3; q++) {
                int l  = lane + 32 * q;
                int yl = sy[q * 32 + lane];
                float dnl = __ldcg(g_dist + n * B + l);
                if (yl != yp && yl != yn)
                    s += fmaxf(M - dnl + 0.1f, 0.0f);
            }
        }
#pragma unroll
        for (int o = 16; o; o >>= 1) s += __shfl_xor_sync(0xffffffffu, s, o);

        if (lane == 0) {
            float c = trip * (1.0f / 96.0f) + s * (1.0f / 9216.0f);   // c >= 0
            unsigned long long inc = (unsigned long long)__float2ll_rn(c * FP_SCALE);
            atomicAdd(&g_acc, inc);
            __threadfence();                      // my add visible before my ticket
            unsigned t2 = atomicAdd(&g_count2, 1u);
            if (t2 == B - 1) {                    // every block is past the spin
                unsigned long long tot = atomicAdd(&g_acc, 0ull);
                out[0]   = (float)((double)tot * FP_INV_SCALE);
                g_acc    = 0ull;                  // reset for next graph replay
                g_count  = 0u;
                g_count2 = 0u;
                __threadfence();
            }
        }
    }
}

// ---------------------------------------------------------------------------
extern "C" void kernel_launch(void* const* d_in, const int* in_sizes, int n_in,
                              void* d_out, int out_size) {
    (void)in_sizes; (void)n_in; (void)out_size;
    const float* embs = (const float*)d_in[0];
    const int*   idt  = (const int*)d_in[1];   // int32 view; layout autodetected
    float*       out  = (float*)d_out;

    k_all<<<B, 1024>>>(embs, idt, out);
}

// round 16
// speedup vs baseline: 1.0021x; 1.0021x over previous
#include <cuda_runtime.h>
#include <math.h>

#define B 96
#define D 512

// ---------------- device scratch (no allocations allowed) ----------------
__device__ unsigned long long g_acc   = 0ull;  // fixed-point (2^38) loss accumulator
__device__ unsigned int       g_count = 0u;    // completion ticket

#define FP_SCALE     274877906944.0f           /* 2^38 */
#define FP_INV_SCALE (1.0 / 274877906944.0)

// ---------------------------------------------------------------------------
// Single kernel, 96 fully independent blocks (no grid sync of any kind).
// Block a:
//   pass 1 : dist row a (warp w -> cols w, w+32, w+64), smem only
//   mine   : batch-hard pos/neg for row a (warp 0)
//   pass 2 : recompute dist rows p and n locally (2 dots per column)
//   epi    : M = max_{b!=p, y_b==y_p} d[b,p];  s = sum_l lmask * relu(M-d[n,l]+0.1)
//   fold   : deterministic int64 fixed-point atomic; last ticket writes out.
// ---------------------------------------------------------------------------
__global__ __launch_bounds__(1024, 1)
void k_all(const float* __restrict__ embs, const int* __restrict__ raw,
           float* __restrict__ out) {
    __shared__ float4 srowA[D / 4];    // 2 KB each
    __shared__ float4 srowP[D / 4];
    __shared__ float4 srowN[D / 4];
    __shared__ float  drow[B], dpv[B], dnv[B];
    __shared__ int    sy[B];
    __shared__ int    s_bad, s_p, s_n;
    __shared__ float  s_trip;

    const int a    = blockIdx.x;
    const int tid  = threadIdx.x;
    const int w    = tid >> 5;
    const int lane = tid & 31;

    if (tid < D / 4) srowA[tid] = ((const float4*)(embs + (size_t)a * D))[tid];
    if (tid == 0)    s_bad = 0;
    __syncthreads();

    // identity layout autodetect (int64-LE pairs look like (v<16, 0));
    // reads stay within the first 96 int32s -> safe in both layouts.
    if (tid < 48) {
        int lo = raw[2 * tid], hi = raw[2 * tid + 1];
        if (hi != 0 || (unsigned)lo >= 16u) s_bad = 1;   // benign race, same value
    }

    // ---- pass 1: dist row a ----
#pragma unroll
    for (int c = 0; c < 3; c++) {
        const int j = w + 32 * c;
        const float4* rj = (const float4*)(embs + (size_t)j * D);
        float s0 = 0.f, s1 = 0.f, s2 = 0.f, s3 = 0.f;
#pragma unroll
        for (int u = 0; u < 4; u++) {
            float4 x = srowA[lane + 32 * u];
            float4 b = rj[lane + 32 * u];
            float d0 = x.x - b.x, d1 = x.y - b.y, d2 = x.z - b.z, d3 = x.w - b.w;
            s0 += d0 * d0; s1 += d1 * d1; s2 += d2 * d2; s3 += d3 * d3;
        }
        float s = (s0 + s1) + (s2 + s3);
#pragma unroll
        for (int o = 16; o; o >>= 1) s += __shfl_xor_sync(0xffffffffu, s, o);
        if (lane == 0)
            drow[j] = (a == j || s <= 0.0f) ? 0.0f : sqrtf(s);   // ref zero-handling
    }
    __syncthreads();                  // drow + s_bad ready
    if (tid < B) sy[tid] = s_bad ? raw[tid] : raw[2 * tid];
    __syncthreads();

    // ---- mining for row a (warp 0) ----
    if (w == 0) {
        const int yi = sy[a];
        float dv[3]; int yv[3];
#pragma unroll
        for (int q = 0; q < 3; q++) {
            int j = lane + 32 * q;
            dv[q] = drow[j];
            yv[q] = sy[j];
        }
        // unmasked row max (for the an_dist offset)
        float maxd = fmaxf(fmaxf(dv[0], dv[1]), dv[2]);
#pragma unroll
        for (int o = 16; o; o >>= 1)
            maxd = fmaxf(maxd, __shfl_xor_sync(0xffffffffu, maxd, o));

        // hardest positive: argmax over mask_ap*d, first-occurrence ties
        float pbest = -1.0f; int pidx = 1 << 20;
#pragma unroll
        for (int q = 0; q < 3; q++) {
            int j = lane + 32 * q;
            float apv = (j != a && yv[q] == yi) ? dv[q] : 0.0f;
            if (apv > pbest) { pbest = apv; pidx = j; }   // strict > keeps smallest j per lane
        }
#pragma unroll
        for (int o = 16; o; o >>= 1) {
            float ov = __shfl_xor_sync(0xffffffffu, pbest, o);
            int   oi = __shfl_xor_sync(0xffffffffu, pidx, o);
            if (ov > pbest || (ov == pbest && oi < pidx)) { pbest = ov; pidx = oi; }
        }

        // hardest negative: argmin over d + maxd*(1-mask_an), first-occurrence ties
        float nbest = 3.4e38f; int nidx = 1 << 20;
#pragma unroll
        for (int q = 0; q < 3; q++) {
            int j = lane + 32 * q;
            float anv = (yv[q] != yi) ? dv[q] : dv[q] + maxd;
            if (anv < nbest) { nbest = anv; nidx = j; }
        }
#pragma unroll
        for (int o = 16; o; o >>= 1) {
            float ov = __shfl_xor_sync(0xffffffffu, nbest, o);
            int   oi = __shfl_xor_sync(0xffffffffu, nidx, o);
            if (ov < nbest || (ov == nbest && oi < nidx)) { nbest = ov; nidx = oi; }
        }

        if (lane == 0) {
            s_trip = fmaxf(pbest - nbest + 0.2f, 0.0f);
            s_p    = pidx;
            s_n    = nidx;
        }
    }
    __syncthreads();

    const int p = s_p, n = s_n;

    // ---- stage rows p and n ----
    if (tid < D / 4)
        srowP[tid] = ((const float4*)(embs + (size_t)p * D))[tid];
    else if (tid < D / 2)
        srowN[tid - D / 4] = ((const float4*)(embs + (size_t)n * D))[tid - D / 4];
    __syncthreads();

    // ---- pass 2: dist rows p and n (two dots per streamed column) ----
#pragma unroll
    for (int c = 0; c < 3; c++) {
        const int j = w + 32 * c;
        const float4* rj = (const float4*)(embs + (size_t)j * D);
        float p0 = 0.f, p1 = 0.f, p2 = 0.f, p3 = 0.f;
        float n0 = 0.f, n1 = 0.f, n2 = 0.f, n3 = 0.f;
#pragma unroll
        for (int u = 0; u < 4; u++) {
            float4 b  = rj[lane + 32 * u];
            float4 xp = srowP[lane + 32 * u];
            float4 xn = srowN[lane + 32 * u];
            float e;
            e = xp.x - b.x; p0 += e * e;  e = xp.y - b.y; p1 += e * e;
            e = xp.z - b.z; p2 += e * e;  e = xp.w - b.w; p3 += e * e;
            e = xn.x - b.x; n0 += e * e;  e = xn.y - b.y; n1 += e * e;
            e = xn.z - b.z; n2 += e * e;  e = xn.w - b.w; n3 += e * e;
        }
        float sp = (p0 + p1) + (p2 + p3);
        float sn = (n0 + n1) + (n2 + n3);
#pragma unroll
        for (int o = 16; o; o >>= 1) {
            sp += __shfl_xor_sync(0xffffffffu, sp, o);
            sn += __shfl_xor_sync(0xffffffffu, sn, o);
        }
        if (lane == 0) {
            dpv[j] = (j == p || sp <= 0.0f) ? 0.0f : sqrtf(sp);
            dnv[j] = (j == n || sn <= 0.0f) ? 0.0f : sqrtf(sn);
        }
    }
    __syncthreads();

    // ---- epilogue: inter term + fold (warp 0) ----
    if (w == 0) {
        const int yp = sy[p], yn = sy[n];

        float M = -1.0f;              // stays -1 iff no valid b (empty positive set)
#pragma unroll
        for (int q = 0; q < 3; q++) {
            int b = lane + 32 * q;
            if (b != p && sy[b] == yp) M = fmaxf(M, dpv[b]);
        }
#pragma unroll
        for (int o = 16; o; o >>= 1)
            M = fmaxf(M, __shfl_xor_sync(0xffffffffu, M, o));

        float s = 0.0f;
        if (M >= 0.0f && yp != yn) {
#pragma unroll
            for (int q = 0; q < 3; q++) {
                int l  = lane + 32 * q;
                int yl = sy[l];
                if (yl != yp && yl != yn)
                    s += fmaxf(M - dnv[l] + 0.1f, 0.0f);
            }
        }
#pragma unroll
        for (int o = 16; o; o >>= 1) s += __shfl_xor_sync(0xffffffffu, s, o);

        if (lane == 0) {
            float c = s_trip * (1.0f / 96.0f) + s * (1.0f / 9216.0f);   // c >= 0
            unsigned long long inc = (unsigned long long)__float2ll_rn(c * FP_SCALE);
            atomicAdd(&g_acc, inc);                    // exact integer add: deterministic
            __threadfence();                           // my add visible before my ticket
            unsigned t = atomicAdd(&g_count, 1u);
            if (t == B - 1) {                          // all 96 contributions are in
                unsigned long long tot = atomicAdd(&g_acc, 0ull);
                out[0]  = (float)((double)tot * FP_INV_SCALE);
                g_acc   = 0ull;                        // reset for next graph replay
                g_count = 0u;
                __threadfence();
            }
        }
    }
}

// ---------------------------------------------------------------------------
extern "C" void kernel_launch(void* const* d_in, const int* in_sizes, int n_in,
                              void* d_out, int out_size) {
    (void)in_sizes; (void)n_in; (void)out_size;
    const float* embs = (const float*)d_in[0];
    const int*   idt  = (const int*)d_in[1];   // int32 view; layout autodetected
    float*       out  = (float*)d_out;

    k_all<<<B, 1024>>>(embs, idt, out);
}

// round 17
// speedup vs baseline: 1.1597x; 1.1572x over previous
#include <cuda_runtime.h>
#include <math.h>

#define B 96
#define D 512
#define RPB 4                 // rows staged per dist block
#define GX (B / RPB)          // 24
#define GY 3                  // 32 columns per block-y

// ---------------- device scratch (no allocations allowed) ----------------
__device__ float              g_dist[B * B];
__device__ unsigned long long g_acc   = 0ull;  // fixed-point (2^38) loss accumulator
__device__ unsigned int       g_count = 0u;    // completion ticket

#define FP_SCALE     274877906944.0f           /* 2^38 */
#define FP_INV_SCALE (1.0 / 274877906944.0)

// ---------------------------------------------------------------------------
// Kernel 1: tiled pairwise distances, minimal L2 traffic (~5.2 MB total).
// Block (ib, jb): stages RPB=4 rows (8 KB), warp w streams column
// j = jb*32 + w once and produces dist for all 4 staged rows (dot-form).
// Bitwise-symmetric: (i,j) and (j,i) accumulate identical products in
// identical order, so row p == column p exactly.
// ---------------------------------------------------------------------------
__global__ __launch_bounds__(1024, 1)
void k_dist(const float* __restrict__ embs) {
    __shared__ float4 srow[RPB * (D / 4)];   // 8 KB
    __shared__ float  s_ni[RPB];

    const int tid  = threadIdx.x;
    const int w    = tid >> 5;
    const int lane = tid & 31;
    const int i0   = blockIdx.x * RPB;

    if (tid < RPB * (D / 4)) {
        int r = tid >> 7, c = tid & 127;
        srow[tid] = ((const float4*)(embs + (size_t)(i0 + r) * D))[c];
    }
    __syncthreads();

    // norms of staged rows (warps 0..3) — same op order as the nj below
    if (w < RPB) {
        float acc = 0.0f;
#pragma unroll
        for (int c = 0; c < 4; c++) {
            float4 a = srow[w * 128 + lane + 32 * c];
            acc += a.x * a.x + a.y * a.y + a.z * a.z + a.w * a.w;
        }
#pragma unroll
        for (int o = 16; o; o >>= 1) acc += __shfl_xor_sync(0xffffffffu, acc, o);
        if (lane == 0) s_ni[w] = acc;
    }
    __syncthreads();

    const int j = blockIdx.y * 32 + w;
    const float4* rj = (const float4*)(embs + (size_t)j * D);
    float s0 = 0.f, s1 = 0.f, s2 = 0.f, s3 = 0.f, nj = 0.f;
#pragma unroll
    for (int c = 0; c < 4; c++) {
        float4 b  = rj[lane + 32 * c];
        nj += b.x * b.x + b.y * b.y + b.z * b.z + b.w * b.w;
        float4 a0 = srow[  0 + lane + 32 * c];
        float4 a1 = srow[128 + lane + 32 * c];
        float4 a2 = srow[256 + lane + 32 * c];
        float4 a3 = srow[384 + lane + 32 * c];
        s0 += a0.x * b.x + a0.y * b.y + a0.z * b.z + a0.w * b.w;
        s1 += a1.x * b.x + a1.y * b.y + a1.z * b.z + a1.w * b.w;
        s2 += a2.x * b.x + a2.y * b.y + a2.z * b.z + a2.w * b.w;
        s3 += a3.x * b.x + a3.y * b.y + a3.z * b.z + a3.w * b.w;
    }
#pragma unroll
    for (int o = 16; o; o >>= 1) {
        s0 += __shfl_xor_sync(0xffffffffu, s0, o);
        s1 += __shfl_xor_sync(0xffffffffu, s1, o);
        s2 += __shfl_xor_sync(0xffffffffu, s2, o);
        s3 += __shfl_xor_sync(0xffffffffu, s3, o);
        nj += __shfl_xor_sync(0xffffffffu, nj, o);
    }
    if (lane < RPB) {
        float s = (lane == 0) ? s0 : (lane == 1) ? s1 : (lane == 2) ? s2 : s3;
        int   i = i0 + lane;
        float v = fmaxf(s_ni[lane] + nj - 2.0f * s, 0.0f);    // ref: sq + sq - 2 dot, clamped
        g_dist[i * B + j] = (i == j || v <= 0.0f) ? 0.0f : sqrtf(v);  // ref zero-handling
    }
}

// ---------------------------------------------------------------------------
// Kernel 2: per-anchor everything. 96 blocks x 1 warp. Block a:
//   mine row a (batch-hard, first-occurrence ties) -> trip, p, n
//   M = max_{b != p, y_b == y_p} d[b,p]   (row p == column p by symmetry)
//   s = sum_l [y_l!=y_p & y_l!=y_n] * relu(M - d[n,l] + 0.1)   (0 if no pos / y_p==y_n)
//   fold trip/96 + s/9216 into a deterministic int64 fixed-point accumulator;
//   the last-arriving block writes out[0] and resets scratch for replay.
// ---------------------------------------------------------------------------
__global__ __launch_bounds__(32, 32)
void k_epi(const int* __restrict__ raw, float* __restrict__ out) {
    const int a    = blockIdx.x;
    const int lane = threadIdx.x;

    // identity layout autodetect (int64-LE pairs look like (v<16, 0));
    // reads stay within the first 96 int32s -> safe in both layouts.
    int bad;
    {
        int lo = raw[2 * lane], hi = raw[2 * lane + 1];
        int b  = (hi != 0) || ((unsigned)lo >= 16u);
        if (lane < 16) {
            int lo2 = raw[2 * (lane + 32)], hi2 = raw[2 * (lane + 32) + 1];
            b |= (hi2 != 0) || ((unsigned)lo2 >= 16u);
        }
        bad = __any_sync(0xffffffffu, b);
    }

    const int yi = bad ? raw[a] : raw[2 * a];
    float dv[3]; int yv[3];
#pragma unroll
    for (int q = 0; q < 3; q++) {
        int j = lane + 32 * q;
        dv[q] = g_dist[a * B + j];
        yv[q] = bad ? raw[j] : raw[2 * j];
    }

    // unmasked row max (for the an_dist offset)
    float maxd = fmaxf(fmaxf(dv[0], dv[1]), dv[2]);
#pragma unroll
    for (int o = 16; o; o >>= 1)
        maxd = fmaxf(maxd, __shfl_xor_sync(0xffffffffu, maxd, o));

    // hardest positive: argmax over mask_ap*d, first-occurrence ties
    float pbest = -1.0f; int pidx = 1 << 20;
#pragma unroll
    for (int q = 0; q < 3; q++) {
        int j = lane + 32 * q;
        float apv = (j != a && yv[q] == yi) ? dv[q] : 0.0f;
        if (apv > pbest) { pbest = apv; pidx = j; }   // strict > keeps smallest j per lane
    }
#pragma unroll
    for (int o = 16; o; o >>= 1) {
        float ov = __shfl_xor_sync(0xffffffffu, pbest, o);
        int   oi = __shfl_xor_sync(0xffffffffu, pidx, o);
        if (ov > pbest || (ov == pbest && oi < pidx)) { pbest = ov; pidx = oi; }
    }

    // hardest negative: argmin over d + maxd*(1-mask_an), first-occurrence ties
    float nbest = 3.4e38f; int nidx = 1 << 20;
#pragma unroll
    for (int q = 0; q < 3; q++) {
        int j = lane + 32 * q;
        float anv = (yv[q] != yi) ? dv[q] : dv[q] + maxd;
        if (anv < nbest) { nbest = anv; nidx = j; }
    }
#pragma unroll
    for (int o = 16; o; o >>= 1) {
        float ov = __shfl_xor_sync(0xffffffffu, nbest, o);
        int   oi = __shfl_xor_sync(0xffffffffu, nidx, o);
        if (ov < nbest || (ov == nbest && oi < nidx)) { nbest = ov; nidx = oi; }
    }

    const float trip = fmaxf(pbest - nbest + 0.2f, 0.0f);
    const int   p = pidx, n = nidx;
    const int   yp = bad ? raw[p] : raw[2 * p];
    const int   yn = bad ? raw[n] : raw[2 * n];

    // M over column p == row p (bitwise symmetric dist)
    float M = -1.0f;                  // stays -1 iff no valid b (empty positive set)
#pragma unroll
    for (int q = 0; q < 3; q++) {
        int bidx = lane + 32 * q;
        float dpb = g_dist[p * B + bidx];
        if (bidx != p && yv[q] == yp) M = fmaxf(M, dpb);
    }
#pragma unroll
    for (int o = 16; o; o >>= 1)
        M = fmaxf(M, __shfl_xor_sync(0xffffffffu, M, o));

    float s = 0.0f;
    if (M >= 0.0f && yp != yn) {
#pragma unroll
        for (int q = 0; q < 3; q++) {
            int l = lane + 32 * q;
            float dnl = g_dist[n * B + l];
            if (yv[q] != yp && yv[q] != yn)
                s += fmaxf(M - dnl + 0.1f, 0.0f);
        }
    }
#pragma unroll
    for (int o = 16; o; o >>= 1) s += __shfl_xor_sync(0xffffffffu, s, o);

    if (lane == 0) {
        float c = trip * (1.0f / 96.0f) + s * (1.0f / 9216.0f);   // c >= 0
        unsigned long long inc = (unsigned long long)__float2ll_rn(c * FP_SCALE);
        atomicAdd(&g_acc, inc);                 // exact integer add: deterministic
        __threadfence();                        // my add visible before my ticket
        unsigned t = atomicAdd(&g_count, 1u);
        if (t == B - 1) {                       // all 96 contributions are in
            unsigned long long tot = atomicAdd(&g_acc, 0ull);
            out[0]  = (float)((double)tot * FP_INV_SCALE);
            g_acc   = 0ull;                     // reset for next graph replay
            g_count = 0u;
            __threadfence();
        }
    }
}

// ---------------------------------------------------------------------------
extern "C" void kernel_launch(void* const* d_in, const int* in_sizes, int n_in,
                              void* d_out, int out_size) {
    (void)in_sizes; (void)n_in; (void)out_size;
    const float* embs = (const float*)d_in[0];
    const int*   idt  = (const int*)d_in[1];   // int32 view; layout autodetected
    float*       out  = (float*)d_out;

    k_dist<<<dim3(GX, GY), 1024>>>(embs);
    k_epi<<<B, 32>>>(idt, out);
}